// round 4
// baseline (speedup 1.0000x reference)
#include <cuda_runtime.h>
#include <cstdint>

// VolumeSDFRenderer — shape-agnostic version.
//   sigma = ALPHA * LaplaceCDF(-sd; BETA)
//   w_p   = exp(-cumsum_{<p} sigma*delta) - exp(-cumsum_{<=p} sigma*delta)
//   out_color[n,c] = sum_p w[n,p] * color[n,p,c];  geometry = zeros [N,P,3]
//
// N and P are derived at launch from out_size and input sizes:
//   S = N*P (size of sd/lengths), out_size = 3N + 3NP (concat) or 3N (color only)
// One warp per ray; P processed in tiles of 32 samples with a carried
// cumulative optical depth. All loads 128B/warp coalesced.

#define ALPHA     10.0f
#define INV_BETA  20.0f     // 1/0.05
#define FAR_DELTA 1e10f

__device__ int g_c0_is_len;

__global__ void classify_kernel(const float* __restrict__ c0, int P) {
    // row 0 sorted non-decreasing and positive => sample_lengths
    bool ok = c0[0] > 0.0f;
    for (int i = 1; i < P; i++) ok = ok && (c0[i] >= c0[i - 1]) && (c0[i] > 0.0f);
    g_c0_is_len = ok ? 1 : 0;
}

__device__ __forceinline__ float sdf_density(float sd) {
    float s = -sd;
    float e = 0.5f * __expf(-fabsf(s) * INV_BETA);
    return ALPHA * ((s <= 0.0f) ? e : (1.0f - e));
}

__global__ __launch_bounds__(256)
void volsdf_kernel(const float* __restrict__ c0,
                   const float* __restrict__ c1,
                   const float* __restrict__ color,
                   float* __restrict__ out_color,
                   float* __restrict__ geometry,   // may be null
                   int n_rays, int P)
{
    const unsigned FULL = 0xffffffffu;
    int ray  = (blockIdx.x * blockDim.x + threadIdx.x) >> 5;
    int lane = threadIdx.x & 31;
    if (ray >= n_rays) return;

    const float* sd = g_c0_is_len ? c1 : c0;
    const float* ln = g_c0_is_len ? c0 : c1;

    const size_t base = (size_t)ray * P;

    float carry = 0.0f;            // cumulative optical depth before this tile
    float r = 0.f, g = 0.f, b = 0.f;

    for (int t = 0; t < P; t += 32) {
        int i = t + lane;                       // sample index (i < P always: P%32==0 assumed; guard anyway)
        bool in = (i < P);
        bool last = (i == P - 1);

        float sdi = in ? sd[base + i] : 0.f;
        float li  = in ? ln[base + i] : 0.f;
        float ln1 = (in && !last) ? ln[base + i + 1] : 0.f;

        float delta = last ? FAR_DELTA : (ln1 - li);
        float a = in ? (sdf_density(sdi) * delta) : 0.f;

        // inclusive warp scan of a
        float v = a;
        #pragma unroll
        for (int o = 1; o < 32; o <<= 1) {
            float tq = __shfl_up_sync(FULL, v, o);
            if (lane >= o) v += tq;
        }
        float ve = v - a;                       // exclusive
        float pe = carry + ve;
        float pi = carry + v;
        float w  = __expf(-pe) - __expf(-pi);

        carry += __shfl_sync(FULL, v, 31);      // tile total

        if (in) {
            const float* cp = color + (base + i) * 3;
            r += w * cp[0];
            g += w * cp[1];
            b += w * cp[2];
        }
    }

    // zero this ray's geometry slice (3P floats, P%4==0 -> float4)
    if (geometry) {
        float4* gz = reinterpret_cast<float4*>(geometry + base * 3);
        int nvec = (3 * P) >> 2;
        const float4 z4 = make_float4(0.f, 0.f, 0.f, 0.f);
        for (int k = lane; k < nvec; k += 32) gz[k] = z4;
    }

    // warp reduction
    #pragma unroll
    for (int o = 16; o > 0; o >>= 1) {
        r += __shfl_xor_sync(FULL, r, o);
        g += __shfl_xor_sync(FULL, g, o);
        b += __shfl_xor_sync(FULL, b, o);
    }

    if (lane == 0) {
        float* oc = out_color + (size_t)ray * 3;
        oc[0] = r; oc[1] = g; oc[2] = b;
    }
}

extern "C" void kernel_launch(void* const* d_in, const int* in_sizes, int n_in,
                              void* d_out, int out_size)
{
    // color = the 3x-sized input
    int color_idx = 0;
    for (int i = 1; i < 3; i++)
        if (in_sizes[i] > in_sizes[color_idx]) color_idx = i;
    int c0_idx = -1, c1_idx = -1;
    for (int i = 0; i < 3; i++) {
        if (i == color_idx) continue;
        if (c0_idx < 0) c0_idx = i; else c1_idx = i;
    }

    const float* color = (const float*)d_in[color_idx];
    const float* cand0 = (const float*)d_in[c0_idx];
    const float* cand1 = (const float*)d_in[c1_idx];

    long long S = in_sizes[c0_idx];           // N * P
    long long O = out_size;

    // Derive N (rays): concat layout => O = 3N + 3S; color-only => O = 3N.
    long long N;
    bool has_geom;
    if (O / 3 > S) { N = O / 3 - S; has_geom = true; }
    else           { N = O / 3;     has_geom = false; }
    if (N <= 0 || (S % N) != 0) {             // fallback: assume P = 128
        N = S / 128; has_geom = (O / 3 > S);
    }
    int P = (int)(S / N);
    int n_rays = (int)N;

    float* out_color = (float*)d_out;
    float* geometry  = has_geom ? ((float*)d_out + (size_t)n_rays * 3) : nullptr;

    classify_kernel<<<1, 1>>>(cand0, P);

    int threads = 256;                        // 8 warps = 8 rays / block
    long long total_threads = (long long)n_rays * 32;
    int blocks = (int)((total_threads + threads - 1) / threads);
    volsdf_kernel<<<blocks, threads>>>(cand0, cand1, color, out_color, geometry,
                                       n_rays, P);
}